// round 4
// baseline (speedup 1.0000x reference)
#include <cuda_runtime.h>
#include <cstdint>

#define N_NODES 128
#define F_IN    128
#define HID     64
#define N_CLS   40
#define NB      4
#define XPAD    132   // 128 + 4 pad -> conflict-free A-fragment LDS
#define WPAD    72    // 64 + 8 pad  -> conflict-free B-fragment LDS

// Precomputed normalized adjacency and its square (scratch: __device__ globals, no allocation)
__device__ float g_An[N_NODES * N_NODES];
__device__ float g_A2[N_NODES * N_NODES];

// ---------------------------------------------------------------------------
// helpers
// ---------------------------------------------------------------------------
__device__ __forceinline__ unsigned f2tf_u(float f) {
    unsigned u;
    asm("cvt.rna.tf32.f32 %0, %1;" : "=r"(u) : "f"(f));
    return u;
}

// 3xTF32 split: v ~= hi + lo, both tf32-representable. hi*hi+hi*lo+lo*hi
// recovers ~21 effective mantissa bits (error ~2^-22, fp32-class).
__device__ __forceinline__ void split_tf32(float v, unsigned& hi, unsigned& lo) {
    hi = f2tf_u(v);
    lo = f2tf_u(v - __uint_as_float(hi));
}

__device__ __forceinline__ void mma_tf32(float* c, const unsigned* a, unsigned b0, unsigned b1) {
    asm volatile(
        "mma.sync.aligned.m16n8k8.row.col.f32.tf32.tf32.f32 "
        "{%0,%1,%2,%3}, {%4,%5,%6,%7}, {%8,%9}, {%0,%1,%2,%3};"
        : "+f"(c[0]), "+f"(c[1]), "+f"(c[2]), "+f"(c[3])
        : "r"(a[0]), "r"(a[1]), "r"(a[2]), "r"(a[3]), "r"(b0), "r"(b1));
}

__device__ __forceinline__ void cp_async16(void* dst, const void* src) {
    unsigned d = (unsigned)__cvta_generic_to_shared(dst);
    asm volatile("cp.async.cg.shared.global [%0], [%1], 16;" :: "r"(d), "l"(src) : "memory");
}
__device__ __forceinline__ void cp_commit() { asm volatile("cp.async.commit_group;" ::: "memory"); }
__device__ __forceinline__ void cp_wait0()  { asm volatile("cp.async.wait_group 0;" ::: "memory"); }

// ---------------------------------------------------------------------------
// Kernel 0: build A_norm = D^-1/2 (A + I) D^-1/2 from tril edge weights
// ---------------------------------------------------------------------------
__global__ void build_anorm_kernel(const float* __restrict__ ew)
{
    __shared__ float dinv[N_NODES];
    const int i = threadIdx.x;
    float s = 0.f;
    for (int j = 0; j < N_NODES; ++j) {
        int hi = i > j ? i : j;
        int lo = i > j ? j : i;
        float a = ew[hi * (hi + 1) / 2 + lo] + (j == i ? 1.f : 0.f);
        s += a;
    }
    dinv[i] = (s > 0.f) ? rsqrtf(s) : 0.f;
    __syncthreads();
    const float di = dinv[i];
    for (int j = 0; j < N_NODES; ++j) {
        int hi = i > j ? i : j;
        int lo = i > j ? j : i;
        float a = ew[hi * (hi + 1) / 2 + lo] + (j == i ? 1.f : 0.f);
        g_An[i * N_NODES + j] = di * a * dinv[j];
    }
}

// ---------------------------------------------------------------------------
// Kernel 1: A2 = A_norm @ A_norm   (128 blocks x 128 threads, coalesced)
// ---------------------------------------------------------------------------
__global__ void compute_a2_kernel()
{
    __shared__ float rowi[N_NODES];
    const int i = blockIdx.x;
    const int j = threadIdx.x;
    rowi[j] = g_An[i * N_NODES + j];
    __syncthreads();
    float s = 0.f;
#pragma unroll 8
    for (int k = 0; k < N_NODES; ++k)
        s += rowi[k] * g_An[k * N_NODES + j];
    g_A2[i * N_NODES + j] = s;
}

// ---------------------------------------------------------------------------
// Main fused kernel: per batch  out = relu(pool(relu(A2 (X W) + lb)) + cb) Fc + fb
// One CTA (256 thr) processes NB batches; 3xTF32 mma.sync GEMMs in smem.
// All smem operands stay full fp32; hi/lo split happens at fragment load.
// ---------------------------------------------------------------------------
struct SMem {
    float Xs[N_NODES][XPAD];    // X tile (fp32 via cp.async)
    float A2s[N_NODES][XPAD];   // A2, fp32
    float Ws[F_IN][WPAD];       // lin_w, fp32 (B operand layout [k][n])
    float Ys[N_NODES][WPAD];    // Y = X@W, fp32 (B operand for GEMM2)
    float pooled[HID];
    float lb[HID];
    float cw[N_NODES];
};

__global__ void __launch_bounds__(256, 1)
dgcnn_main(const float* __restrict__ x,
           const float* __restrict__ lin_w,
           const float* __restrict__ lin_b,
           const float* __restrict__ conv_w,
           const float* __restrict__ conv_b,
           const float* __restrict__ fc_w,
           const float* __restrict__ fc_b,
           float* __restrict__ out,
           int Btot)
{
    extern __shared__ char smraw[];
    SMem* sm = reinterpret_cast<SMem*>(smraw);

    const int tid  = threadIdx.x;
    const int lane = tid & 31;
    const int warp = tid >> 5;
    const int g    = lane >> 2;   // 0..7
    const int tg   = lane & 3;    // 0..3
    const int wM   = warp >> 1;   // 0..3 : 32 rows each
    const int wN   = warp & 1;    // 0..1 : 32 cols each
    const int bbase = blockIdx.x * NB;

    // ---- prefetch first X (async) ----
    if (bbase < Btot) {
        const float* xb = x + (size_t)bbase * (N_NODES * F_IN);
#pragma unroll
        for (int c = 0; c < 16; ++c) {
            int i4 = tid + (c << 8);          // 4096 16B chunks
            int r  = i4 >> 5;
            int cc = (i4 & 31) << 2;
            cp_async16(&sm->Xs[r][cc], xb + r * F_IN + cc);
        }
        cp_commit();
    }

    // ---- fill A2 (fp32) ----
#pragma unroll
    for (int c = 0; c < 16; ++c) {
        int i4 = tid + (c << 8);
        int r  = i4 >> 5;
        int cc = (i4 & 31) << 2;
        *reinterpret_cast<float4*>(&sm->A2s[r][cc]) =
            *reinterpret_cast<const float4*>(g_A2 + r * N_NODES + cc);
    }
    // ---- fill W (fp32) ----
#pragma unroll
    for (int c = 0; c < 8; ++c) {
        int i4 = tid + (c << 8);              // 2048 chunks
        int r  = i4 >> 4;
        int cc = (i4 & 15) << 2;
        *reinterpret_cast<float4*>(&sm->Ws[r][cc]) =
            *reinterpret_cast<const float4*>(lin_w + r * HID + cc);
    }
    if (tid < HID)     sm->lb[tid] = lin_b[tid];
    if (tid < N_NODES) sm->cw[tid] = conv_w[tid];

#pragma unroll 1
    for (int it = 0; it < NB; ++it) {
        const int b = bbase + it;
        if (b >= Btot) break;

        cp_wait0();
        __syncthreads();                       // Xs ready; prologue/prev-iter done
        if (tid < HID) sm->pooled[tid] = 0.f;

        float acc[2][4][4];

        // ============ GEMM1: Y = X @ W  (3xTF32, split at frag load) =========
#pragma unroll
        for (int mt = 0; mt < 2; ++mt)
#pragma unroll
            for (int nt = 0; nt < 4; ++nt)
#pragma unroll
                for (int j = 0; j < 4; ++j) acc[mt][nt][j] = 0.f;

#pragma unroll
        for (int k = 0; k < 16; ++k) {
            unsigned ah[2][4], al[2][4];
#pragma unroll
            for (int mt = 0; mt < 2; ++mt) {
                const float* xr = &sm->Xs[wM * 32 + mt * 16 + g][k * 8 + tg];
                split_tf32(xr[0],            ah[mt][0], al[mt][0]);
                split_tf32(xr[8 * XPAD],     ah[mt][1], al[mt][1]);
                split_tf32(xr[4],            ah[mt][2], al[mt][2]);
                split_tf32(xr[8 * XPAD + 4], ah[mt][3], al[mt][3]);
            }
#pragma unroll
            for (int nt = 0; nt < 4; ++nt) {
                int colb = wN * 32 + nt * 8 + g;
                unsigned b0h, b0l, b1h, b1l;
                split_tf32(sm->Ws[k * 8 + tg][colb],     b0h, b0l);
                split_tf32(sm->Ws[k * 8 + tg + 4][colb], b1h, b1l);
#pragma unroll
                for (int mt = 0; mt < 2; ++mt) {
                    mma_tf32(acc[mt][nt], ah[mt], b0h, b1h);
                    mma_tf32(acc[mt][nt], ah[mt], b0l, b1l);
                    mma_tf32(acc[mt][nt], al[mt], b0h, b1h);
                }
            }
        }
        __syncthreads();                       // all warps done reading Xs

        // ---- store Y (full fp32), conflict-free 64-bit stores ----
#pragma unroll
        for (int mt = 0; mt < 2; ++mt) {
            int r = wM * 32 + mt * 16 + g;
#pragma unroll
            for (int nt = 0; nt < 4; ++nt) {
                int cc = wN * 32 + nt * 8 + 2 * tg;
                float2 v;
                v.x = acc[mt][nt][0]; v.y = acc[mt][nt][1];
                *reinterpret_cast<float2*>(&sm->Ys[r][cc]) = v;
                v.x = acc[mt][nt][2]; v.y = acc[mt][nt][3];
                *reinterpret_cast<float2*>(&sm->Ys[r + 8][cc]) = v;
            }
        }
        __syncthreads();                       // Ys visible

        // ---- prefetch next batch X while GEMM2 runs ----
        if (it + 1 < NB && b + 1 < Btot) {
            const float* xb = x + (size_t)(b + 1) * (N_NODES * F_IN);
#pragma unroll
            for (int c = 0; c < 16; ++c) {
                int i4 = tid + (c << 8);
                int r  = i4 >> 5;
                int cc = (i4 & 31) << 2;
                cp_async16(&sm->Xs[r][cc], xb + r * F_IN + cc);
            }
            cp_commit();
        }

        // ============ GEMM2: Z = A2 @ Y  (3xTF32) ============================
#pragma unroll
        for (int mt = 0; mt < 2; ++mt)
#pragma unroll
            for (int nt = 0; nt < 4; ++nt)
#pragma unroll
                for (int j = 0; j < 4; ++j) acc[mt][nt][j] = 0.f;

#pragma unroll
        for (int k = 0; k < 16; ++k) {
            unsigned ah[2][4], al[2][4];
#pragma unroll
            for (int mt = 0; mt < 2; ++mt) {
                const float* ar = &sm->A2s[wM * 32 + mt * 16 + g][k * 8 + tg];
                split_tf32(ar[0],            ah[mt][0], al[mt][0]);
                split_tf32(ar[8 * XPAD],     ah[mt][1], al[mt][1]);
                split_tf32(ar[4],            ah[mt][2], al[mt][2]);
                split_tf32(ar[8 * XPAD + 4], ah[mt][3], al[mt][3]);
            }
#pragma unroll
            for (int nt = 0; nt < 4; ++nt) {
                int colb = wN * 32 + nt * 8 + g;
                unsigned b0h, b0l, b1h, b1l;
                split_tf32(sm->Ys[k * 8 + tg][colb],     b0h, b0l);
                split_tf32(sm->Ys[k * 8 + tg + 4][colb], b1h, b1l);
#pragma unroll
                for (int mt = 0; mt < 2; ++mt) {
                    mma_tf32(acc[mt][nt], ah[mt], b0h, b1h);
                    mma_tf32(acc[mt][nt], ah[mt], b0l, b1l);
                    mma_tf32(acc[mt][nt], al[mt], b0h, b1h);
                }
            }
        }

        // ================= epilogue: bias+relu, conv_w pooling ===============
        float p[8];
#pragma unroll
        for (int i = 0; i < 8; ++i) p[i] = 0.f;
#pragma unroll
        for (int mt = 0; mt < 2; ++mt) {
            int r = wM * 32 + mt * 16 + g;
            float c0 = sm->cw[r], c1 = sm->cw[r + 8];
#pragma unroll
            for (int nt = 0; nt < 4; ++nt) {
                int cc = wN * 32 + nt * 8 + 2 * tg;
                float l0 = sm->lb[cc], l1 = sm->lb[cc + 1];
                p[2 * nt]     += fmaxf(acc[mt][nt][0] + l0, 0.f) * c0
                               + fmaxf(acc[mt][nt][2] + l0, 0.f) * c1;
                p[2 * nt + 1] += fmaxf(acc[mt][nt][1] + l1, 0.f) * c0
                               + fmaxf(acc[mt][nt][3] + l1, 0.f) * c1;
            }
        }
#pragma unroll
        for (int i = 0; i < 8; ++i) {
            p[i] += __shfl_xor_sync(0xffffffffu, p[i], 4);
            p[i] += __shfl_xor_sync(0xffffffffu, p[i], 8);
            p[i] += __shfl_xor_sync(0xffffffffu, p[i], 16);
        }
        if (lane < 4) {
#pragma unroll
            for (int nt = 0; nt < 4; ++nt) {
                atomicAdd(&sm->pooled[wN * 32 + nt * 8 + 2 * lane],     p[2 * nt]);
                atomicAdd(&sm->pooled[wN * 32 + nt * 8 + 2 * lane + 1], p[2 * nt + 1]);
            }
        }
        __syncthreads();                       // pooled complete

        // ---- relu(+conv_b), FC 64->40, write out ----
        if (tid < N_CLS) {
            float cb = conv_b[0];
            float o = fc_b[tid];
#pragma unroll
            for (int h = 0; h < HID; ++h) {
                float ph = fmaxf(sm->pooled[h] + cb, 0.f);
                o += ph * __ldg(fc_w + h * N_CLS + tid);
            }
            out[(size_t)b * N_CLS + tid] = o;
        }
    }
}

// ---------------------------------------------------------------------------
extern "C" void kernel_launch(void* const* d_in, const int* in_sizes, int n_in,
                              void* d_out, int out_size)
{
    const float* x   = (const float*)d_in[0];
    const float* ew  = (const float*)d_in[1];
    const float* lw  = (const float*)d_in[2];
    const float* lb  = (const float*)d_in[3];
    const float* cw  = (const float*)d_in[4];
    const float* cb  = (const float*)d_in[5];
    const float* fw  = (const float*)d_in[6];
    const float* fb  = (const float*)d_in[7];
    float* outp      = (float*)d_out;

    const int Btot = in_sizes[0] / (N_NODES * F_IN);

    build_anorm_kernel<<<1, N_NODES>>>(ew);
    compute_a2_kernel<<<N_NODES, N_NODES>>>();

    cudaFuncSetAttribute(dgcnn_main, cudaFuncAttributeMaxDynamicSharedMemorySize,
                         (int)sizeof(SMem));
    const int grid = (Btot + NB - 1) / NB;
    dgcnn_main<<<grid, 256, sizeof(SMem)>>>(x, lw, lb, cw, cb, fw, fb, outp, Btot);
}

// round 6
// speedup vs baseline: 1.0423x; 1.0423x over previous
#include <cuda_runtime.h>
#include <cstdint>

#define N_NODES 128
#define F_IN    128
#define HID     64
#define N_CLS   40
#define NB      4
#define XPAD    132   // 128 + 4 pad -> conflict-free A-fragment LDS
#define WPAD    72    // 64 + 8 pad  -> conflict-free B-fragment LDS

// Precomputed normalized adjacency and its square (scratch: __device__ globals, no allocation)
__device__ float g_An[N_NODES * N_NODES];
__device__ float g_A2[N_NODES * N_NODES];

// ---------------------------------------------------------------------------
// helpers
// ---------------------------------------------------------------------------
__device__ __forceinline__ unsigned f2tf_u(float f) {
    unsigned u;
    asm("cvt.rna.tf32.f32 %0, %1;" : "=r"(u) : "f"(f));
    return u;
}

// 3xTF32 split: v ~= hi + lo, both tf32-representable. hi*hi+hi*lo+lo*hi
// recovers ~21 effective mantissa bits (error ~2^-22, fp32-class).
__device__ __forceinline__ void split_tf32(float v, unsigned& hi, unsigned& lo) {
    hi = f2tf_u(v);
    lo = f2tf_u(v - __uint_as_float(hi));
}

// NOTE: non-volatile on purpose — lets ptxas reorder/software-pipeline HMMAs
// so the 3 split-passes don't form a back-to-back RAW chain on one accumulator.
__device__ __forceinline__ void mma_tf32(float* c, const unsigned* a, unsigned b0, unsigned b1) {
    asm("mma.sync.aligned.m16n8k8.row.col.f32.tf32.tf32.f32 "
        "{%0,%1,%2,%3}, {%4,%5,%6,%7}, {%8,%9}, {%0,%1,%2,%3};"
        : "+f"(c[0]), "+f"(c[1]), "+f"(c[2]), "+f"(c[3])
        : "r"(a[0]), "r"(a[1]), "r"(a[2]), "r"(a[3]), "r"(b0), "r"(b1));
}

__device__ __forceinline__ void cp_async16(void* dst, const void* src) {
    unsigned d = (unsigned)__cvta_generic_to_shared(dst);
    asm volatile("cp.async.cg.shared.global [%0], [%1], 16;" :: "r"(d), "l"(src) : "memory");
}
__device__ __forceinline__ void cp_commit() { asm volatile("cp.async.commit_group;" ::: "memory"); }
__device__ __forceinline__ void cp_wait0()  { asm volatile("cp.async.wait_group 0;" ::: "memory"); }

// ---------------------------------------------------------------------------
// Kernel 0: build A_norm = D^-1/2 (A + I) D^-1/2 from tril edge weights
// One block, 1024 threads: warp-parallel degree reduction + parallel fill.
// ---------------------------------------------------------------------------
__global__ void __launch_bounds__(1024, 1) build_anorm_kernel(const float* __restrict__ ew)
{
    __shared__ float dinv[N_NODES];
    const int tid = threadIdx.x;

    // Phase 1: degrees. 8 threads per row, 16 elements each, shfl-reduce.
    {
        const int row = tid >> 3;        // 0..127
        const int sub = tid & 7;         // 0..7
        float s = 0.f;
#pragma unroll
        for (int q = 0; q < 16; ++q) {
            int j = sub * 16 + q;
            int hi = row > j ? row : j;
            int lo = row > j ? j : row;
            s += ew[hi * (hi + 1) / 2 + lo] + (j == row ? 1.f : 0.f);
        }
        s += __shfl_xor_sync(0xffffffffu, s, 1);
        s += __shfl_xor_sync(0xffffffffu, s, 2);
        s += __shfl_xor_sync(0xffffffffu, s, 4);
        if (sub == 0) dinv[row] = (s > 0.f) ? rsqrtf(s) : 0.f;
    }
    __syncthreads();

    // Phase 2: fill A_norm, 16 elements per thread.
#pragma unroll
    for (int q = 0; q < 16; ++q) {
        int idx = tid + (q << 10);       // 0..16383
        int i = idx >> 7;
        int j = idx & 127;
        int hi = i > j ? i : j;
        int lo = i > j ? j : i;
        float a = ew[hi * (hi + 1) / 2 + lo] + (j == i ? 1.f : 0.f);
        g_An[idx] = dinv[i] * a * dinv[j];
    }
}

// ---------------------------------------------------------------------------
// Kernel 1: A2 = A_norm @ A_norm   (128 blocks x 128 threads, coalesced)
// ---------------------------------------------------------------------------
__global__ void compute_a2_kernel()
{
    __shared__ float rowi[N_NODES];
    const int i = blockIdx.x;
    const int j = threadIdx.x;
    rowi[j] = g_An[i * N_NODES + j];
    __syncthreads();
    float s = 0.f;
#pragma unroll 8
    for (int k = 0; k < N_NODES; ++k)
        s += rowi[k] * g_An[k * N_NODES + j];
    g_A2[i * N_NODES + j] = s;
}

// ---------------------------------------------------------------------------
// Main fused kernel: per batch  out = relu(pool(relu(A2 (X W) + lb)) + cb) Fc + fb
// One CTA (256 thr) processes NB batches; 3xTF32 mma.sync GEMMs in smem.
// All smem operands stay full fp32; hi/lo split happens at fragment load.
// ---------------------------------------------------------------------------
struct SMem {
    float Xs[N_NODES][XPAD];    // X tile (fp32 via cp.async)
    float A2s[N_NODES][XPAD];   // A2, fp32
    float Ws[F_IN][WPAD];       // lin_w, fp32 (B operand layout [k][n])
    float Ys[N_NODES][WPAD];    // Y = X@W, fp32 (B operand for GEMM2)
    float pooled[HID];
    float lb[HID];
    float cw[N_NODES];
};

__global__ void __launch_bounds__(256, 1)
dgcnn_main(const float* __restrict__ x,
           const float* __restrict__ lin_w,
           const float* __restrict__ lin_b,
           const float* __restrict__ conv_w,
           const float* __restrict__ conv_b,
           const float* __restrict__ fc_w,
           const float* __restrict__ fc_b,
           float* __restrict__ out,
           int Btot)
{
    extern __shared__ char smraw[];
    SMem* sm = reinterpret_cast<SMem*>(smraw);

    const int tid  = threadIdx.x;
    const int lane = tid & 31;
    const int warp = tid >> 5;
    const int g    = lane >> 2;   // 0..7
    const int tg   = lane & 3;    // 0..3
    const int wM   = warp >> 1;   // 0..3 : 32 rows each
    const int wN   = warp & 1;    // 0..1 : 32 cols each
    const int bbase = blockIdx.x * NB;

    // ---- prefetch first X (async) ----
    if (bbase < Btot) {
        const float* xb = x + (size_t)bbase * (N_NODES * F_IN);
#pragma unroll
        for (int c = 0; c < 16; ++c) {
            int i4 = tid + (c << 8);          // 4096 16B chunks
            int r  = i4 >> 5;
            int cc = (i4 & 31) << 2;
            cp_async16(&sm->Xs[r][cc], xb + r * F_IN + cc);
        }
        cp_commit();
    }

    // ---- fill A2 (fp32) ----
#pragma unroll
    for (int c = 0; c < 16; ++c) {
        int i4 = tid + (c << 8);
        int r  = i4 >> 5;
        int cc = (i4 & 31) << 2;
        *reinterpret_cast<float4*>(&sm->A2s[r][cc]) =
            *reinterpret_cast<const float4*>(g_A2 + r * N_NODES + cc);
    }
    // ---- fill W (fp32) ----
#pragma unroll
    for (int c = 0; c < 8; ++c) {
        int i4 = tid + (c << 8);              // 2048 chunks
        int r  = i4 >> 4;
        int cc = (i4 & 15) << 2;
        *reinterpret_cast<float4*>(&sm->Ws[r][cc]) =
            *reinterpret_cast<const float4*>(lin_w + r * HID + cc);
    }
    if (tid < HID)     sm->lb[tid] = lin_b[tid];
    if (tid < N_NODES) sm->cw[tid] = conv_w[tid];

#pragma unroll 1
    for (int it = 0; it < NB; ++it) {
        const int b = bbase + it;
        if (b >= Btot) break;

        cp_wait0();
        __syncthreads();                       // Xs ready; prologue/prev-iter done
        if (tid < HID) sm->pooled[tid] = 0.f;

        float acc[2][4][4];

        // ============ GEMM1: Y = X @ W  (3xTF32, split at frag load) =========
#pragma unroll
        for (int mt = 0; mt < 2; ++mt)
#pragma unroll
            for (int nt = 0; nt < 4; ++nt)
#pragma unroll
                for (int j = 0; j < 4; ++j) acc[mt][nt][j] = 0.f;

#pragma unroll
        for (int k = 0; k < 16; ++k) {
            unsigned ah[2][4], al[2][4], bh[4][2], bl[4][2];
#pragma unroll
            for (int mt = 0; mt < 2; ++mt) {
                const float* xr = &sm->Xs[wM * 32 + mt * 16 + g][k * 8 + tg];
                split_tf32(xr[0],            ah[mt][0], al[mt][0]);
                split_tf32(xr[8 * XPAD],     ah[mt][1], al[mt][1]);
                split_tf32(xr[4],            ah[mt][2], al[mt][2]);
                split_tf32(xr[8 * XPAD + 4], ah[mt][3], al[mt][3]);
            }
#pragma unroll
            for (int nt = 0; nt < 4; ++nt) {
                int colb = wN * 32 + nt * 8 + g;
                split_tf32(sm->Ws[k * 8 + tg][colb],     bh[nt][0], bl[nt][0]);
                split_tf32(sm->Ws[k * 8 + tg + 4][colb], bh[nt][1], bl[nt][1]);
            }
            // pass 1: hi*hi over 8 independent accumulators
#pragma unroll
            for (int nt = 0; nt < 4; ++nt) {
                mma_tf32(acc[0][nt], ah[0], bh[nt][0], bh[nt][1]);
                mma_tf32(acc[1][nt], ah[1], bh[nt][0], bh[nt][1]);
            }
            // pass 2: hi*lo
#pragma unroll
            for (int nt = 0; nt < 4; ++nt) {
                mma_tf32(acc[0][nt], ah[0], bl[nt][0], bl[nt][1]);
                mma_tf32(acc[1][nt], ah[1], bl[nt][0], bl[nt][1]);
            }
            // pass 3: lo*hi
#pragma unroll
            for (int nt = 0; nt < 4; ++nt) {
                mma_tf32(acc[0][nt], al[0], bh[nt][0], bh[nt][1]);
                mma_tf32(acc[1][nt], al[1], bh[nt][0], bh[nt][1]);
            }
        }
        __syncthreads();                       // all warps done reading Xs

        // ---- store Y (full fp32), conflict-free 64-bit stores ----
#pragma unroll
        for (int mt = 0; mt < 2; ++mt) {
            int r = wM * 32 + mt * 16 + g;
#pragma unroll
            for (int nt = 0; nt < 4; ++nt) {
                int cc = wN * 32 + nt * 8 + 2 * tg;
                float2 v;
                v.x = acc[mt][nt][0]; v.y = acc[mt][nt][1];
                *reinterpret_cast<float2*>(&sm->Ys[r][cc]) = v;
                v.x = acc[mt][nt][2]; v.y = acc[mt][nt][3];
                *reinterpret_cast<float2*>(&sm->Ys[r + 8][cc]) = v;
            }
        }
        __syncthreads();                       // Ys visible

        // ---- prefetch next batch X while GEMM2 runs ----
        if (it + 1 < NB && b + 1 < Btot) {
            const float* xb = x + (size_t)(b + 1) * (N_NODES * F_IN);
#pragma unroll
            for (int c = 0; c < 16; ++c) {
                int i4 = tid + (c << 8);
                int r  = i4 >> 5;
                int cc = (i4 & 31) << 2;
                cp_async16(&sm->Xs[r][cc], xb + r * F_IN + cc);
            }
            cp_commit();
        }

        // ============ GEMM2: Z = A2 @ Y  (3xTF32) ============================
#pragma unroll
        for (int mt = 0; mt < 2; ++mt)
#pragma unroll
            for (int nt = 0; nt < 4; ++nt)
#pragma unroll
                for (int j = 0; j < 4; ++j) acc[mt][nt][j] = 0.f;

#pragma unroll
        for (int k = 0; k < 16; ++k) {
            unsigned ah[2][4], al[2][4], bh[4][2], bl[4][2];
#pragma unroll
            for (int mt = 0; mt < 2; ++mt) {
                const float* ar = &sm->A2s[wM * 32 + mt * 16 + g][k * 8 + tg];
                split_tf32(ar[0],            ah[mt][0], al[mt][0]);
                split_tf32(ar[8 * XPAD],     ah[mt][1], al[mt][1]);
                split_tf32(ar[4],            ah[mt][2], al[mt][2]);
                split_tf32(ar[8 * XPAD + 4], ah[mt][3], al[mt][3]);
            }
#pragma unroll
            for (int nt = 0; nt < 4; ++nt) {
                int colb = wN * 32 + nt * 8 + g;
                split_tf32(sm->Ys[k * 8 + tg][colb],     bh[nt][0], bl[nt][0]);
                split_tf32(sm->Ys[k * 8 + tg + 4][colb], bh[nt][1], bl[nt][1]);
            }
#pragma unroll
            for (int nt = 0; nt < 4; ++nt) {
                mma_tf32(acc[0][nt], ah[0], bh[nt][0], bh[nt][1]);
                mma_tf32(acc[1][nt], ah[1], bh[nt][0], bh[nt][1]);
            }
#pragma unroll
            for (int nt = 0; nt < 4; ++nt) {
                mma_tf32(acc[0][nt], ah[0], bl[nt][0], bl[nt][1]);
                mma_tf32(acc[1][nt], ah[1], bl[nt][0], bl[nt][1]);
            }
#pragma unroll
            for (int nt = 0; nt < 4; ++nt) {
                mma_tf32(acc[0][nt], al[0], bh[nt][0], bh[nt][1]);
                mma_tf32(acc[1][nt], al[1], bh[nt][0], bh[nt][1]);
            }
        }

        // ================= epilogue: bias+relu, conv_w pooling ===============
        float p[8];
#pragma unroll
        for (int i = 0; i < 8; ++i) p[i] = 0.f;
#pragma unroll
        for (int mt = 0; mt < 2; ++mt) {
            int r = wM * 32 + mt * 16 + g;
            float c0 = sm->cw[r], c1 = sm->cw[r + 8];
#pragma unroll
            for (int nt = 0; nt < 4; ++nt) {
                int cc = wN * 32 + nt * 8 + 2 * tg;
                float l0 = sm->lb[cc], l1 = sm->lb[cc + 1];
                p[2 * nt]     += fmaxf(acc[mt][nt][0] + l0, 0.f) * c0
                               + fmaxf(acc[mt][nt][2] + l0, 0.f) * c1;
                p[2 * nt + 1] += fmaxf(acc[mt][nt][1] + l1, 0.f) * c0
                               + fmaxf(acc[mt][nt][3] + l1, 0.f) * c1;
            }
        }
#pragma unroll
        for (int i = 0; i < 8; ++i) {
            p[i] += __shfl_xor_sync(0xffffffffu, p[i], 4);
            p[i] += __shfl_xor_sync(0xffffffffu, p[i], 8);
            p[i] += __shfl_xor_sync(0xffffffffu, p[i], 16);
        }
        if (lane < 4) {
#pragma unroll
            for (int nt = 0; nt < 4; ++nt) {
                atomicAdd(&sm->pooled[wN * 32 + nt * 8 + 2 * lane],     p[2 * nt]);
                atomicAdd(&sm->pooled[wN * 32 + nt * 8 + 2 * lane + 1], p[2 * nt + 1]);
            }
        }
        __syncthreads();                       // pooled complete

        // ---- relu(+conv_b), FC 64->40, write out ----
        if (tid < N_CLS) {
            float cb = conv_b[0];
            float o = fc_b[tid];
#pragma unroll
            for (int h = 0; h < HID; ++h) {
                float ph = fmaxf(sm->pooled[h] + cb, 0.f);
                o += ph * __ldg(fc_w + h * N_CLS + tid);
            }
            out[(size_t)b * N_CLS + tid] = o;
        }
    }
}

// ---------------------------------------------------------------------------
extern "C" void kernel_launch(void* const* d_in, const int* in_sizes, int n_in,
                              void* d_out, int out_size)
{
    const float* x   = (const float*)d_in[0];
    const float* ew  = (const float*)d_in[1];
    const float* lw  = (const float*)d_in[2];
    const float* lb  = (const float*)d_in[3];
    const float* cw  = (const float*)d_in[4];
    const float* cb  = (const float*)d_in[5];
    const float* fw  = (const float*)d_in[6];
    const float* fb  = (const float*)d_in[7];
    float* outp      = (float*)d_out;

    const int Btot = in_sizes[0] / (N_NODES * F_IN);

    build_anorm_kernel<<<1, 1024>>>(ew);
    compute_a2_kernel<<<N_NODES, N_NODES>>>();

    cudaFuncSetAttribute(dgcnn_main, cudaFuncAttributeMaxDynamicSharedMemorySize,
                         (int)sizeof(SMem));
    const int grid = (Btot + NB - 1) / NB;
    dgcnn_main<<<grid, 256, sizeof(SMem)>>>(x, lw, lb, cw, cb, fw, fb, outp, Btot);
}

// round 7
// speedup vs baseline: 1.7299x; 1.6598x over previous
#include <cuda_runtime.h>
#include <cstdint>

#define N_NODES 128
#define F_IN    128
#define HID     64
#define N_CLS   40
#define NB      4
#define XPAD    132   // fp32 X rows: 132*4B -> 4-bank row shift, LDS.64 frags at 2/bank uniform
#define APAD    68    // packed A2 rows (u32): 4-bank shift -> conflict-free LDS.32 A-frags
#define WPAD    72    // packed W rows (u32): 8-bank shift -> conflict-free LDS.32 B-frags
#define YPAD    68    // fp32 Y rows: conflict-free B-side LDS.32 in GEMM2

// Precomputed normalized adjacency and its square (scratch: __device__ globals)
__device__ float g_An[N_NODES * N_NODES];
__device__ float g_A2[N_NODES * N_NODES];

// ---------------------------------------------------------------------------
// helpers
// ---------------------------------------------------------------------------
// Split (v0,v1) into packed bf16x2 hi + packed bf16x2 mid.
// Low 16 bits hold v0 (lower-k element), high 16 hold v1 — matches the
// m16n8k16 A/B fragment packing convention.
__device__ __forceinline__ unsigned pack_split(float v0, float v1, unsigned& mid) {
    unsigned h;
    asm("cvt.rn.bf16x2.f32 %0, %1, %2;" : "=r"(h) : "f"(v1), "f"(v0)); // first src -> upper half
    float h0 = __uint_as_float(h << 16);
    float h1 = __uint_as_float(h & 0xffff0000u);
    float m0 = v0 - h0;
    float m1 = v1 - h1;
    asm("cvt.rn.bf16x2.f32 %0, %1, %2;" : "=r"(mid) : "f"(m1), "f"(m0));
    return h;
}

// Non-volatile: let ptxas schedule/pipeline HMMAs freely.
__device__ __forceinline__ void mma_bf16(float* c, const unsigned* a, unsigned b0, unsigned b1) {
    asm("mma.sync.aligned.m16n8k16.row.col.f32.bf16.bf16.f32 "
        "{%0,%1,%2,%3}, {%4,%5,%6,%7}, {%8,%9}, {%0,%1,%2,%3};"
        : "+f"(c[0]), "+f"(c[1]), "+f"(c[2]), "+f"(c[3])
        : "r"(a[0]), "r"(a[1]), "r"(a[2]), "r"(a[3]), "r"(b0), "r"(b1));
}

__device__ __forceinline__ void cp_async16(void* dst, const void* src) {
    unsigned d = (unsigned)__cvta_generic_to_shared(dst);
    asm volatile("cp.async.cg.shared.global [%0], [%1], 16;" :: "r"(d), "l"(src) : "memory");
}
__device__ __forceinline__ void cp_commit() { asm volatile("cp.async.commit_group;" ::: "memory"); }
__device__ __forceinline__ void cp_wait0()  { asm volatile("cp.async.wait_group 0;" ::: "memory"); }

// ---------------------------------------------------------------------------
// Kernel 0: build A_norm = D^-1/2 (A + I) D^-1/2 from tril edge weights
// ---------------------------------------------------------------------------
__global__ void __launch_bounds__(1024, 1) build_anorm_kernel(const float* __restrict__ ew)
{
    __shared__ float dinv[N_NODES];
    const int tid = threadIdx.x;
    {
        const int row = tid >> 3;
        const int sub = tid & 7;
        float s = 0.f;
#pragma unroll
        for (int q = 0; q < 16; ++q) {
            int j = sub * 16 + q;
            int hi = row > j ? row : j;
            int lo = row > j ? j : row;
            s += ew[hi * (hi + 1) / 2 + lo] + (j == row ? 1.f : 0.f);
        }
        s += __shfl_xor_sync(0xffffffffu, s, 1);
        s += __shfl_xor_sync(0xffffffffu, s, 2);
        s += __shfl_xor_sync(0xffffffffu, s, 4);
        if (sub == 0) dinv[row] = (s > 0.f) ? rsqrtf(s) : 0.f;
    }
    __syncthreads();
#pragma unroll
    for (int q = 0; q < 16; ++q) {
        int idx = tid + (q << 10);
        int i = idx >> 7;
        int j = idx & 127;
        int hi = i > j ? i : j;
        int lo = i > j ? j : i;
        float a = ew[hi * (hi + 1) / 2 + lo] + (j == i ? 1.f : 0.f);
        g_An[idx] = dinv[i] * a * dinv[j];
    }
}

// ---------------------------------------------------------------------------
// Kernel 1: A2 = A_norm @ A_norm
// ---------------------------------------------------------------------------
__global__ void compute_a2_kernel()
{
    __shared__ float rowi[N_NODES];
    const int i = blockIdx.x;
    const int j = threadIdx.x;
    rowi[j] = g_An[i * N_NODES + j];
    __syncthreads();
    float s = 0.f;
#pragma unroll 8
    for (int k = 0; k < N_NODES; ++k)
        s += rowi[k] * g_An[k * N_NODES + j];
    g_A2[i * N_NODES + j] = s;
}

// ---------------------------------------------------------------------------
// Main fused kernel. bf16 split-emulated GEMMs (hh + hm + mh), m16n8k16.
// A2 and W pre-split once per CTA into packed bf16x2 k-pair arrays.
// X (per batch, cp.async) and Y (GEMM1 result) split inline at frag load.
// ---------------------------------------------------------------------------
struct SMem {
    float    Xs[N_NODES][XPAD];     // fp32 X (cp.async dst)
    unsigned A2h[N_NODES][APAD];    // packed bf16x2: (A2[r][2c], A2[r][2c+1]) hi
    unsigned A2m[N_NODES][APAD];    // mid
    unsigned Wh[F_IN / 2][WPAD];    // packed bf16x2: (W[2kp][n], W[2kp+1][n]) hi
    unsigned Wm[F_IN / 2][WPAD];    // mid
    float    Ys[N_NODES][YPAD];     // fp32 Y = X@W
    float pooled[HID];
    float lb[HID];
    float cw[N_NODES];
};

__global__ void __launch_bounds__(256, 1)
dgcnn_main(const float* __restrict__ x,
           const float* __restrict__ lin_w,
           const float* __restrict__ lin_b,
           const float* __restrict__ conv_w,
           const float* __restrict__ conv_b,
           const float* __restrict__ fc_w,
           const float* __restrict__ fc_b,
           float* __restrict__ out,
           int Btot)
{
    extern __shared__ char smraw[];
    SMem* sm = reinterpret_cast<SMem*>(smraw);

    const int tid  = threadIdx.x;
    const int lane = tid & 31;
    const int warp = tid >> 5;
    const int g    = lane >> 2;   // 0..7
    const int tg   = lane & 3;    // 0..3
    const int wM   = warp >> 1;   // 0..3 : 32 rows each
    const int wN   = warp & 1;    // 0..1 : 32 cols each
    const int bbase = blockIdx.x * NB;

    // ---- prefetch first X (async) ----
    if (bbase < Btot) {
        const float* xb = x + (size_t)bbase * (N_NODES * F_IN);
#pragma unroll
        for (int c = 0; c < 16; ++c) {
            int i4 = tid + (c << 8);
            int r  = i4 >> 5;
            int cc = (i4 & 31) << 2;
            cp_async16(&sm->Xs[r][cc], xb + r * F_IN + cc);
        }
        cp_commit();
    }

    // ---- pre-split A2 into packed bf16x2 hi/mid (32 pairs per thread) ----
#pragma unroll
    for (int q = 0; q < 32; ++q) {
        int p = tid + (q << 8);          // 0..8191
        int r = p >> 6, c = p & 63;
        float2 v = *reinterpret_cast<const float2*>(g_A2 + r * N_NODES + 2 * c);
        unsigned m, h = pack_split(v.x, v.y, m);
        sm->A2h[r][c] = h;
        sm->A2m[r][c] = m;
    }
    // ---- pre-split W (16 pairs per thread) ----
#pragma unroll
    for (int q = 0; q < 16; ++q) {
        int p = tid + (q << 8);          // 0..4095
        int kp = p >> 6, n = p & 63;
        float v0 = lin_w[(2 * kp) * HID + n];
        float v1 = lin_w[(2 * kp + 1) * HID + n];
        unsigned m, h = pack_split(v0, v1, m);
        sm->Wh[kp][n] = h;
        sm->Wm[kp][n] = m;
    }
    if (tid < HID)     sm->lb[tid] = lin_b[tid];
    if (tid < N_NODES) sm->cw[tid] = conv_w[tid];

#pragma unroll 1
    for (int it = 0; it < NB; ++it) {
        const int b = bbase + it;
        if (b >= Btot) break;

        cp_wait0();
        __syncthreads();                       // Xs ready; prologue/prev-iter done
        if (tid < HID) sm->pooled[tid] = 0.f;

        float acc[2][4][4];

        // ============ GEMM1: Y = X @ W  (bf16 split, X inline) ==============
#pragma unroll
        for (int mt = 0; mt < 2; ++mt)
#pragma unroll
            for (int nt = 0; nt < 4; ++nt)
#pragma unroll
                for (int j = 0; j < 4; ++j) acc[mt][nt][j] = 0.f;

#pragma unroll
        for (int kk = 0; kk < 8; ++kk) {
            unsigned ah[2][4], am[2][4], bh[4][2], bm[4][2];
#pragma unroll
            for (int mt = 0; mt < 2; ++mt) {
                const float* xr = &sm->Xs[wM * 32 + mt * 16 + g][16 * kk + 2 * tg];
                float2 v0 = *reinterpret_cast<const float2*>(xr);
                float2 v1 = *reinterpret_cast<const float2*>(xr + 8 * XPAD);
                float2 v2 = *reinterpret_cast<const float2*>(xr + 8);
                float2 v3 = *reinterpret_cast<const float2*>(xr + 8 * XPAD + 8);
                ah[mt][0] = pack_split(v0.x, v0.y, am[mt][0]);
                ah[mt][1] = pack_split(v1.x, v1.y, am[mt][1]);
                ah[mt][2] = pack_split(v2.x, v2.y, am[mt][2]);
                ah[mt][3] = pack_split(v3.x, v3.y, am[mt][3]);
            }
#pragma unroll
            for (int nt = 0; nt < 4; ++nt) {
                int n  = wN * 32 + nt * 8 + g;
                int kp = 8 * kk + tg;
                bh[nt][0] = sm->Wh[kp][n];     bm[nt][0] = sm->Wm[kp][n];
                bh[nt][1] = sm->Wh[kp + 4][n]; bm[nt][1] = sm->Wm[kp + 4][n];
            }
            // pass 1: hi*hi (8 independent accumulators)
#pragma unroll
            for (int nt = 0; nt < 4; ++nt) {
                mma_bf16(acc[0][nt], ah[0], bh[nt][0], bh[nt][1]);
                mma_bf16(acc[1][nt], ah[1], bh[nt][0], bh[nt][1]);
            }
            // pass 2: hi*mid
#pragma unroll
            for (int nt = 0; nt < 4; ++nt) {
                mma_bf16(acc[0][nt], ah[0], bm[nt][0], bm[nt][1]);
                mma_bf16(acc[1][nt], ah[1], bm[nt][0], bm[nt][1]);
            }
            // pass 3: mid*hi
#pragma unroll
            for (int nt = 0; nt < 4; ++nt) {
                mma_bf16(acc[0][nt], am[0], bh[nt][0], bh[nt][1]);
                mma_bf16(acc[1][nt], am[1], bh[nt][0], bh[nt][1]);
            }
        }
        __syncthreads();                       // all warps done reading Xs

        // ---- store Y (fp32), float2 stores ----
#pragma unroll
        for (int mt = 0; mt < 2; ++mt) {
            int r = wM * 32 + mt * 16 + g;
#pragma unroll
            for (int nt = 0; nt < 4; ++nt) {
                int cc = wN * 32 + nt * 8 + 2 * tg;
                float2 v;
                v.x = acc[mt][nt][0]; v.y = acc[mt][nt][1];
                *reinterpret_cast<float2*>(&sm->Ys[r][cc]) = v;
                v.x = acc[mt][nt][2]; v.y = acc[mt][nt][3];
                *reinterpret_cast<float2*>(&sm->Ys[r + 8][cc]) = v;
            }
        }
        __syncthreads();                       // Ys visible

        // ---- prefetch next batch X while GEMM2 runs ----
        if (it + 1 < NB && b + 1 < Btot) {
            const float* xb = x + (size_t)(b + 1) * (N_NODES * F_IN);
#pragma unroll
            for (int c = 0; c < 16; ++c) {
                int i4 = tid + (c << 8);
                int r  = i4 >> 5;
                int cc = (i4 & 31) << 2;
                cp_async16(&sm->Xs[r][cc], xb + r * F_IN + cc);
            }
            cp_commit();
        }

        // ============ GEMM2: Z = A2 @ Y  (A2 pre-split, Y inline) ===========
#pragma unroll
        for (int mt = 0; mt < 2; ++mt)
#pragma unroll
            for (int nt = 0; nt < 4; ++nt)
#pragma unroll
                for (int j = 0; j < 4; ++j) acc[mt][nt][j] = 0.f;

#pragma unroll
        for (int kk = 0; kk < 8; ++kk) {
            unsigned ah[2][4], am[2][4], bh[4][2], bm[4][2];
#pragma unroll
            for (int mt = 0; mt < 2; ++mt) {
                int row = wM * 32 + mt * 16 + g;
                int kp  = 8 * kk + tg;
                ah[mt][0] = sm->A2h[row][kp];         am[mt][0] = sm->A2m[row][kp];
                ah[mt][1] = sm->A2h[row + 8][kp];     am[mt][1] = sm->A2m[row + 8][kp];
                ah[mt][2] = sm->A2h[row][kp + 4];     am[mt][2] = sm->A2m[row][kp + 4];
                ah[mt][3] = sm->A2h[row + 8][kp + 4]; am[mt][3] = sm->A2m[row + 8][kp + 4];
            }
#pragma unroll
            for (int nt = 0; nt < 4; ++nt) {
                int n  = wN * 32 + nt * 8 + g;
                int r0 = 16 * kk + 2 * tg;
                bh[nt][0] = pack_split(sm->Ys[r0][n],     sm->Ys[r0 + 1][n], bm[nt][0]);
                bh[nt][1] = pack_split(sm->Ys[r0 + 8][n], sm->Ys[r0 + 9][n], bm[nt][1]);
            }
#pragma unroll
            for (int nt = 0; nt < 4; ++nt) {
                mma_bf16(acc[0][nt], ah[0], bh[nt][0], bh[nt][1]);
                mma_bf16(acc[1][nt], ah[1], bh[nt][0], bh[nt][1]);
            }
#pragma unroll
            for (int nt = 0; nt < 4; ++nt) {
                mma_bf16(acc[0][nt], ah[0], bm[nt][0], bm[nt][1]);
                mma_bf16(acc[1][nt], ah[1], bm[nt][0], bm[nt][1]);
            }
#pragma unroll
            for (int nt = 0; nt < 4; ++nt) {
                mma_bf16(acc[0][nt], am[0], bh[nt][0], bh[nt][1]);
                mma_bf16(acc[1][nt], am[1], bh[nt][0], bh[nt][1]);
            }
        }

        // ================= epilogue: bias+relu, conv_w pooling ===============
        float p[8];
#pragma unroll
        for (int i = 0; i < 8; ++i) p[i] = 0.f;
#pragma unroll
        for (int mt = 0; mt < 2; ++mt) {
            int r = wM * 32 + mt * 16 + g;
            float c0 = sm->cw[r], c1 = sm->cw[r + 8];
#pragma unroll
            for (int nt = 0; nt < 4; ++nt) {
                int cc = wN * 32 + nt * 8 + 2 * tg;
                float l0 = sm->lb[cc], l1 = sm->lb[cc + 1];
                p[2 * nt]     += fmaxf(acc[mt][nt][0] + l0, 0.f) * c0
                               + fmaxf(acc[mt][nt][2] + l0, 0.f) * c1;
                p[2 * nt + 1] += fmaxf(acc[mt][nt][1] + l1, 0.f) * c0
                               + fmaxf(acc[mt][nt][3] + l1, 0.f) * c1;
            }
        }
#pragma unroll
        for (int i = 0; i < 8; ++i) {
            p[i] += __shfl_xor_sync(0xffffffffu, p[i], 4);
            p[i] += __shfl_xor_sync(0xffffffffu, p[i], 8);
            p[i] += __shfl_xor_sync(0xffffffffu, p[i], 16);
        }
        if (lane < 4) {
#pragma unroll
            for (int nt = 0; nt < 4; ++nt) {
                atomicAdd(&sm->pooled[wN * 32 + nt * 8 + 2 * lane],     p[2 * nt]);
                atomicAdd(&sm->pooled[wN * 32 + nt * 8 + 2 * lane + 1], p[2 * nt + 1]);
            }
        }
        __syncthreads();                       // pooled complete

        // ---- relu(+conv_b), FC 64->40, write out ----
        if (tid < N_CLS) {
            float cb = conv_b[0];
            float o = fc_b[tid];
#pragma unroll
            for (int h = 0; h < HID; ++h) {
                float ph = fmaxf(sm->pooled[h] + cb, 0.f);
                o += ph * __ldg(fc_w + h * N_CLS + tid);
            }
            out[(size_t)b * N_CLS + tid] = o;
        }
    }
}

// ---------------------------------------------------------------------------
extern "C" void kernel_launch(void* const* d_in, const int* in_sizes, int n_in,
                              void* d_out, int out_size)
{
    const float* x   = (const float*)d_in[0];
    const float* ew  = (const float*)d_in[1];
    const float* lw  = (const float*)d_in[2];
    const float* lb  = (const float*)d_in[3];
    const float* cw  = (const float*)d_in[4];
    const float* cb  = (const float*)d_in[5];
    const float* fw  = (const float*)d_in[6];
    const float* fb  = (const float*)d_in[7];
    float* outp      = (float*)d_out;

    const int Btot = in_sizes[0] / (N_NODES * F_IN);

    build_anorm_kernel<<<1, 1024>>>(ew);
    compute_a2_kernel<<<N_NODES, N_NODES>>>();

    cudaFuncSetAttribute(dgcnn_main, cudaFuncAttributeMaxDynamicSharedMemorySize,
                         (int)sizeof(SMem));
    const int grid = (Btot + NB - 1) / NB;
    dgcnn_main<<<grid, 256, sizeof(SMem)>>>(x, lw, lb, cw, cb, fw, fb, outp, Btot);
}